// round 17
// baseline (speedup 1.0000x reference)
#include <cuda_runtime.h>
#include <cuda_fp16.h>
#include <math.h>
#include <stdint.h>

#define HID     64
#define TWO_H   128
#define TILE    128
#define NTHR    256
#define EPSF    1e-5f
#define SLOPEF  0.2f

#define WP4     34     // weight row stride in uint4 (paired B-frags)
#define APS2    40     // packed activation row stride (uint2 units)
#define MS4     34     // f16x2 message staging row stride (uint32 units)

// shared memory layout (float offsets)
#define OFF_W1P 0        // 32 rows x 34 uint4 = 4352 floats
#define OFF_W2P 4352
#define OFF_W3P 6528
#define OFF_AB  8704     // 64 x 40 uint2 = 5120
#define OFF_MS  13824    // 128 x 34 uint32 = 4352
#define OFF_G1  18176
#define OFF_B1  18304
#define OFF_G2  18432
#define OFF_B2  18496
#define OFF_G3  18560
#define OFF_B3  18624
#define OFF_TG0 18688
#define OFF_TG1 18816
#define OFF_SR0 18944
#define OFF_SR1 19072
#define OFF_EW0 19200
#define OFF_EW1 19328
#define SMEM_FLOATS 19456
#define SMEM_BYTES  (SMEM_FLOATS * 4)   // 77,824 B -> 2 blocks/SM

// -------- scratch --------
#define MAXN 262145
#define MAXE 1048576
#define SCAN_CHUNK 4096
#define MAXCHUNK 128
__device__ int d_cnt[MAXN + 1];
__device__ int d_sorted[MAXE];
__device__ int d_scan_flag[MAXCHUNK];
__device__ int d_scan_agg[MAXCHUNK];
__device__ int d_scan_inc[MAXCHUNK];
__device__ int d_scan_done;
__device__ __align__(16) __half2 d_xh[(size_t)(MAXN - 1) * 32];  // fp16 cache of x

__device__ __forceinline__ unsigned fkey(float v) {
    unsigned u = __float_as_uint(v);
    return u ^ (unsigned)(((int)u >> 31) | 0x80000000);
}
#define KEY_NEG_INF 0x007FFFFFu
#define NEG_INF_F   __int_as_float(0xFF800000)
#define H2_NEG_INF  0xFC00FC00u

__device__ __forceinline__ uint32_t hf2(float hi, float lo) {
    uint32_t r;
    asm("cvt.rn.f16x2.f32 %0, %1, %2;" : "=r"(r) : "f"(hi), "f"(lo));
    return r;
}

__device__ __forceinline__ void mma_f16(float acc[4],
                                        uint32_t a0, uint32_t a1, uint32_t a2, uint32_t a3,
                                        uint32_t b0, uint32_t b1) {
    asm volatile(
        "mma.sync.aligned.m16n8k16.row.col.f32.f16.f16.f32 "
        "{%0,%1,%2,%3}, {%4,%5,%6,%7}, {%8,%9}, {%0,%1,%2,%3};"
        : "+f"(acc[0]), "+f"(acc[1]), "+f"(acc[2]), "+f"(acc[3])
        : "r"(a0), "r"(a1), "r"(a2), "r"(a3), "r"(b0), "r"(b1));
}

// unpack 8 f16 (uint4) to 8 floats
__device__ __forceinline__ void unp8(uint4 v, float* o) {
    const __half2* h = (const __half2*)&v;
    #pragma unroll
    for (int u = 0; u < 4; u++) {
        float2 f = __half22float2(h[u]);
        o[2*u] = f.x; o[2*u+1] = f.y;
    }
}

// ============ prep kernels ============
__global__ void zero_init_kernel(int n, uint4* __restrict__ out, int n4,
                                 const float2* __restrict__ x2, int nxh2) {
    int i = blockIdx.x * blockDim.x + threadIdx.x;
    if (i < n) d_cnt[i] = 0;
    if (i < MAXCHUNK) d_scan_flag[i] = 0;
    if (i == MAXCHUNK) d_scan_done = 0;
    if (i < n4) out[i] = make_uint4(KEY_NEG_INF, KEY_NEG_INF, KEY_NEG_INF, KEY_NEG_INF);
    if (i < nxh2) {
        float2 f = x2[i];
        d_xh[i] = __floats2half2_rn(f.x, f.y);
    }
}

__global__ void hist_kernel(const int* __restrict__ eindex, int E) {
    int i = blockIdx.x * blockDim.x + threadIdx.x;
    if (i < E) atomicAdd(&d_cnt[eindex[E + i] + 1], 1);
}

__global__ void __launch_bounds__(256)
scan_scatter_kernel(const int* __restrict__ eindex, int E, int n, int nchunk) {
    const int t = threadIdx.x, lane = t & 31, w = t >> 5;
    const int bid = blockIdx.x;

    if (bid < nchunk) {
        __shared__ int warp_tot[8];
        __shared__ int excl_sh;
        const int base = bid * SCAN_CHUNK + t * 16;

        int v[16];
        if (base + 15 < n) {
            #pragma unroll
            for (int j = 0; j < 4; j++) {
                int4 qv = *(const int4*)(d_cnt + base + 4 * j);
                v[4*j] = qv.x; v[4*j+1] = qv.y; v[4*j+2] = qv.z; v[4*j+3] = qv.w;
            }
        } else {
            #pragma unroll
            for (int j = 0; j < 16; j++) v[j] = (base + j < n) ? d_cnt[base + j] : 0;
        }
        #pragma unroll
        for (int j = 1; j < 16; j++) v[j] += v[j - 1];

        int s = v[15];
        #pragma unroll
        for (int o = 1; o < 32; o <<= 1) {
            int u = __shfl_up_sync(0xffffffffu, s, o);
            if (lane >= o) s += u;
        }
        if (lane == 31) warp_tot[w] = s;
        __syncthreads();
        if (w == 0) {
            int ws = (lane < 8) ? warp_tot[lane] : 0;
            #pragma unroll
            for (int o = 1; o < 8; o <<= 1) {
                int u = __shfl_up_sync(0xffffffffu, ws, o);
                if (lane >= o) ws += u;
            }
            if (lane < 8) warp_tot[lane] = ws;
        }
        __syncthreads();
        const int block_tot = warp_tot[7];
        const int thr_excl  = (s - v[15]) + (w > 0 ? warp_tot[w - 1] : 0);

        if (t == 0) {
            d_scan_agg[bid] = block_tot;
            __threadfence();
            atomicExch(&d_scan_flag[bid], 1);
            int excl = 0;
            for (int p = bid - 1; p >= 0; ) {
                int f;
                do { f = atomicAdd(&d_scan_flag[p], 0); } while (f == 0);
                if (f == 2) { excl += atomicAdd(&d_scan_inc[p], 0); break; }
                excl += atomicAdd(&d_scan_agg[p], 0);
                p--;
            }
            d_scan_inc[bid] = excl + block_tot;
            __threadfence();
            atomicExch(&d_scan_flag[bid], 2);
            excl_sh = excl;
        }
        __syncthreads();
        const int add = excl_sh + thr_excl;

        if (base + 15 < n) {
            #pragma unroll
            for (int j = 0; j < 4; j++) {
                int4 qv; qv.x = v[4*j] + add; qv.y = v[4*j+1] + add; qv.z = v[4*j+2] + add; qv.w = v[4*j+3] + add;
                *(int4*)(d_cnt + base + 4 * j) = qv;
            }
        } else {
            #pragma unroll
            for (int j = 0; j < 16; j++) if (base + j < n) d_cnt[base + j] = v[j] + add;
        }
        __syncthreads();
        if (t == 0) { __threadfence(); atomicAdd(&d_scan_done, 1); }
    }

    if (t == 0) {
        while (atomicAdd(&d_scan_done, 0) < nchunk) { }
    }
    __syncthreads();
    __threadfence();

    for (int i = bid * 256 + t; i < E; i += gridDim.x * 256) {
        int tg = eindex[E + i];
        int pos = atomicAdd(&d_cnt[tg], 1);
        d_sorted[pos] = i;
    }
}

__global__ void finalize_kernel(const float* __restrict__ x, float* __restrict__ out, int n) {
    int i = blockIdx.x * blockDim.x + threadIdx.x;
    if (i < n) {
        unsigned u = ((const unsigned*)out)[i];
        unsigned bits = (u & 0x80000000u) ? (u ^ 0x80000000u) : ~u;
        float v = __uint_as_float(bits);
        if (isinf(v)) v = 0.0f;
        out[i] = v + x[i];
    }
}

// ============ launch 4: persistent fp16 edge kernel ============
__global__ void __launch_bounds__(NTHR, 2)
edge_kernel(const float* __restrict__ x,
            const float* __restrict__ eweight,
            const int* __restrict__ eindex,
            const float* __restrict__ w1,
            const float* __restrict__ w2,
            const float* __restrict__ w3,
            const float* __restrict__ g1, const float* __restrict__ b1,
            const float* __restrict__ g2, const float* __restrict__ b2,
            const float* __restrict__ g3, const float* __restrict__ b3,
            float* __restrict__ out, int E, int ntiles)
{
    extern __shared__ float sm[];
    uint4*    w1p4 = (uint4*)(sm + OFF_W1P);
    uint4*    w2p4 = (uint4*)(sm + OFF_W2P);
    uint4*    w3p4 = (uint4*)(sm + OFF_W3P);
    uint2*    AB   = (uint2*)(sm + OFF_AB);
    uint32_t* MS16 = (uint32_t*)(sm + OFF_MS);
    float* g1s = sm + OFF_G1;
    float* b1s = sm + OFF_B1;
    float* g2s = sm + OFF_G2;
    float* b2s = sm + OFF_B2;
    float* g3s = sm + OFF_G3;
    float* b3s = sm + OFF_B3;
    int*   tgb[2] = { (int*)(sm + OFF_TG0), (int*)(sm + OFF_TG1) };
    int*   srb[2] = { (int*)(sm + OFF_SR0), (int*)(sm + OFF_SR1) };
    float* ewb[2] = { sm + OFF_EW0, sm + OFF_EW1 };

    const int t    = threadIdx.x;
    const int lane = t & 31;
    const int wid  = t >> 5;
    const int stride = gridDim.x;
    const char* xh = (const char*)d_xh;

    // ---- stage paired fp16 weights ONCE ----
    // GEMM1 k-map: K0(kt,q) = kt<4 ? 16q+4kt : 64+16q+4(kt-4)  (lane-contiguous m-cols)
    {
        uint2* w1p2 = (uint2*)w1p4;
        for (int i = t; i < 2048; i += NTHR) {            // w1: kt 0..7, q, c
            int kt = i >> 8, q = (i >> 6) & 3, c = i & 63;
            int K0 = (kt < 4) ? (16*q + 4*kt) : (64 + 16*q + 4*(kt - 4));
            float4 v = *(const float4*)(w1 + c * TWO_H + K0);
            int nt = c >> 3, g = c & 7;
            w1p2[((kt*4 + q)*WP4 + (nt >> 1)*8 + g)*2 + (nt & 1)] =
                make_uint2(hf2(v.y, v.x), hf2(v.w, v.z));
        }
        // GEMM2/3 keep K0 = 16kt+4q (matches AB packing)
        uint2* w2p2 = (uint2*)w2p4;
        uint2* w3p2 = (uint2*)w3p4;
        for (int i = t; i < 1024; i += NTHR) {            // w2/w3: kt 0..3, q, c
            int kt = i >> 8, q = (i >> 6) & 3, c = i & 63;
            float4 v2 = *(const float4*)(w2 + c * HID + 16 * kt + 4 * q);
            float4 v3 = *(const float4*)(w3 + c * HID + 16 * kt + 4 * q);
            int nt = c >> 3, g = c & 7;
            int idx = ((kt*4 + q)*WP4 + (nt >> 1)*8 + g)*2 + (nt & 1);
            w2p2[idx] = make_uint2(hf2(v2.y, v2.x), hf2(v2.w, v2.z));
            w3p2[idx] = make_uint2(hf2(v3.y, v3.x), hf2(v3.w, v3.z));
        }
    }
    if (t < 128) { g1s[t] = g1[t]; b1s[t] = b1[t]; }
    else if (t < 192) {
        int u = t - 128;
        g2s[u] = g2[u]; b2s[u] = b2[u]; g3s[u] = g3[u]; b3s[u] = b3[u];
    }

    int   p_tgt = -1, p_src = 0;
    float p_ew  = 0.f;
    #define LOAD_META(TL)                                            \
        do {                                                         \
            p_tgt = -1; p_src = 0; p_ew = 0.f;                       \
            if (t < TILE && (TL) < ntiles) {                         \
                int ge = (TL) * TILE + t;                            \
                if (ge < E) {                                        \
                    int eid = d_sorted[ge];                          \
                    p_tgt = eindex[E + eid];                         \
                    p_src = eindex[eid];                             \
                    p_ew  = eweight[eid];                            \
                }                                                    \
            }                                                        \
        } while (0)

    const int tile0 = blockIdx.x;
    LOAD_META(tile0);
    if (t < TILE) { tgb[0][t] = p_tgt; srb[0][t] = p_src; ewb[0][t] = p_ew; }
    LOAD_META(tile0 + stride);

    const int grp  = lane >> 2;
    const int q    = lane & 3;
    const int r_lo = wid * 16 + grp;
    const int r_hi = r_lo + 8;
    const int rp   = wid * 8 + grp;

    int par = 0;
    for (int tile = tile0; tile < ntiles; tile += stride, par ^= 1) {
        __syncthreads();

        if (t < TILE) { tgb[par^1][t] = p_tgt; srb[par^1][t] = p_src; ewb[par^1][t] = p_ew; }
        LOAD_META(tile + 2 * stride);

        const int*   tgs = tgb[par];
        const int*   srs = srb[par];
        const float* ews = ewb[par];

        // ---- f16 gather: lane q owns m-cols {16q..16q+15} and {64+16q..64+16q+15} ----
        float mlo[32], mhi[32];
        const int tg_lo = tgs[r_lo], tg_hi = tgs[r_hi];
        {
            if (tg_lo >= 0) {
                const uint4* xi4 = (const uint4*)(xh + (size_t)tg_lo * 128);
                const uint4* xj4 = (const uint4*)(xh + (size_t)srs[r_lo] * 128);
                float w = ews[r_lo];
                unp8(__ldg(xi4 + 2*q),     mlo);
                unp8(__ldg(xi4 + 2*q + 1), mlo + 8);
                float xj[16];
                unp8(__ldg(xj4 + 2*q),     xj);
                unp8(__ldg(xj4 + 2*q + 1), xj + 8);
                #pragma unroll
                for (int i = 0; i < 16; i++) mlo[16 + i] = w * (xj[i] - mlo[i]);
            } else {
                #pragma unroll
                for (int i = 0; i < 32; i++) mlo[i] = 0.0f;
            }
        }
        {
            if (tg_hi >= 0) {
                const bool same = (tg_hi == tg_lo);
                const uint4* xj4 = (const uint4*)(xh + (size_t)srs[r_hi] * 128);
                float w = ews[r_hi];
                if (same) {
                    #pragma unroll
                    for (int i = 0; i < 16; i++) mhi[i] = mlo[i];   // raw xi reuse (pre-LN)
                } else {
                    const uint4* xi4 = (const uint4*)(xh + (size_t)tg_hi * 128);
                    unp8(__ldg(xi4 + 2*q),     mhi);
                    unp8(__ldg(xi4 + 2*q + 1), mhi + 8);
                }
                float xj[16];
                unp8(__ldg(xj4 + 2*q),     xj);
                unp8(__ldg(xj4 + 2*q + 1), xj + 8);
                #pragma unroll
                for (int i = 0; i < 16; i++) mhi[16 + i] = w * (xj[i] - mhi[i]);
            } else {
                #pragma unroll
                for (int i = 0; i < 32; i++) mhi[i] = 0.0f;
            }
        }

        // ---- LN1 (width 128) in registers ----
        {
            float s_lo = 0.f, q_lo = 0.f, s_hi = 0.f, q_hi = 0.f;
            #pragma unroll
            for (int tt = 0; tt < 32; tt++) {
                s_lo += mlo[tt]; q_lo += mlo[tt] * mlo[tt];
                s_hi += mhi[tt]; q_hi += mhi[tt] * mhi[tt];
            }
            #pragma unroll
            for (int o = 1; o <= 2; o <<= 1) {
                s_lo += __shfl_xor_sync(0xffffffffu, s_lo, o);
                q_lo += __shfl_xor_sync(0xffffffffu, q_lo, o);
                s_hi += __shfl_xor_sync(0xffffffffu, s_hi, o);
                q_hi += __shfl_xor_sync(0xffffffffu, q_hi, o);
            }
            float mu_lo = s_lo * (1.0f / 128.0f);
            float mu_hi = s_hi * (1.0f / 128.0f);
            float r_l   = rsqrtf(fmaxf(q_lo * (1.0f / 128.0f) - mu_lo * mu_lo, 0.0f) + EPSF);
            float r_h   = rsqrtf(fmaxf(q_hi * (1.0f / 128.0f) - mu_hi * mu_hi, 0.0f) + EPSF);
            // m-col of mlo[4kt+j]: kt<4 -> 16q+4kt+j ; kt>=4 -> 64+16q+4(kt-4)+j
            #pragma unroll
            for (int kt = 0; kt < 8; kt++) {
                int c0 = (kt < 4) ? (16*q + 4*kt) : (64 + 16*q + 4*(kt - 4));
                #pragma unroll
                for (int j = 0; j < 4; j++) {
                    float g = g1s[c0 + j], b = b1s[c0 + j];
                    float h0 = (mlo[4*kt+j] - mu_lo) * r_l * g + b;
                    float h1 = (mhi[4*kt+j] - mu_hi) * r_h * g + b;
                    mlo[4*kt+j] = h0 > 0.f ? h0 : SLOPEF * h0;
                    mhi[4*kt+j] = h1 > 0.f ? h1 : SLOPEF * h1;
                }
            }
        }

        float acc[8][4];

        // ===== GEMM1: K=128, 8 fp16 MMA steps; B via paired LDS.128 =====
        #pragma unroll
        for (int nt = 0; nt < 8; nt++)
            #pragma unroll
            for (int j = 0; j < 4; j++) acc[nt][j] = 0.0f;
        #pragma unroll
        for (int kt = 0; kt < 8; kt++) {
            uint32_t a0 = hf2(mlo[4*kt+1], mlo[4*kt]);
            uint32_t a1 = hf2(mhi[4*kt+1], mhi[4*kt]);
            uint32_t a2 = hf2(mlo[4*kt+3], mlo[4*kt+2]);
            uint32_t a3 = hf2(mhi[4*kt+3], mhi[4*kt+2]);
            const uint4* wrow = w1p4 + (kt * 4 + q) * WP4 + grp;
            #pragma unroll
            for (int p = 0; p < 4; p++) {
                uint4 b4 = wrow[p * 8];
                mma_f16(acc[2*p],   a0, a1, a2, a3, b4.x, b4.y);
                mma_f16(acc[2*p+1], a0, a1, a2, a3, b4.z, b4.w);
            }
        }

        // ---- LN2 -> AB ----
        {
            float s_lo = 0.f, q_lo = 0.f, s_hi = 0.f, q_hi = 0.f;
            #pragma unroll
            for (int nt = 0; nt < 8; nt++) {
                s_lo += acc[nt][0] + acc[nt][1];
                q_lo += acc[nt][0]*acc[nt][0] + acc[nt][1]*acc[nt][1];
                s_hi += acc[nt][2] + acc[nt][3];
                q_hi += acc[nt][2]*acc[nt][2] + acc[nt][3]*acc[nt][3];
            }
            #pragma unroll
            for (int o = 1; o <= 2; o <<= 1) {
                s_lo += __shfl_xor_sync(0xffffffffu, s_lo, o);
                q_lo += __shfl_xor_sync(0xffffffffu, q_lo, o);
                s_hi += __shfl_xor_sync(0xffffffffu, s_hi, o);
                q_hi += __shfl_xor_sync(0xffffffffu, q_hi, o);
            }
            float mu_lo = s_lo * (1.0f/64.0f);
            float mu_hi = s_hi * (1.0f/64.0f);
            float r_l   = rsqrtf(fmaxf(q_lo * (1.0f/64.0f) - mu_lo*mu_lo, 0.0f) + EPSF);
            float r_h   = rsqrtf(fmaxf(q_hi * (1.0f/64.0f) - mu_hi*mu_hi, 0.0f) + EPSF);

            #pragma unroll
            for (int nt = 0; nt < 8; nt++) {
                int c0 = nt * 8 + 2 * q;
                float2 g = *(float2*)(g2s + c0);
                float2 b = *(float2*)(b2s + c0);
                float h0 = (acc[nt][0] - mu_lo) * r_l * g.x + b.x;
                float h1 = (acc[nt][1] - mu_lo) * r_l * g.y + b.y;
                float h2 = (acc[nt][2] - mu_hi) * r_h * g.x + b.x;
                float h3 = (acc[nt][3] - mu_hi) * r_h * g.y + b.y;
                h0 = h0 > 0.f ? h0 : SLOPEF * h0;
                h1 = h1 > 0.f ? h1 : SLOPEF * h1;
                h2 = h2 > 0.f ? h2 : SLOPEF * h2;
                h3 = h3 > 0.f ? h3 : SLOPEF * h3;
                AB[rp * APS2 + 4 * nt + q] = make_uint2(hf2(h1, h0), hf2(h3, h2));
            }
        }
        __syncwarp();

        // ===== GEMM2 =====
        #pragma unroll
        for (int nt = 0; nt < 8; nt++)
            #pragma unroll
            for (int j = 0; j < 4; j++) acc[nt][j] = 0.0f;
        {
            const uint2* Ab = AB + rp * APS2;
            #pragma unroll
            for (int kt = 0; kt < 4; kt++) {
                uint4 av = *(const uint4*)(Ab + 8 * kt + 2 * q);
                const uint4* wrow = w2p4 + (kt * 4 + q) * WP4 + grp;
                #pragma unroll
                for (int p = 0; p < 4; p++) {
                    uint4 b4 = wrow[p * 8];
                    mma_f16(acc[2*p],   av.x, av.y, av.z, av.w, b4.x, b4.y);
                    mma_f16(acc[2*p+1], av.x, av.y, av.z, av.w, b4.z, b4.w);
                }
            }
        }
        __syncwarp();

        // ---- LN3 -> AB ----
        {
            float s_lo = 0.f, q_lo = 0.f, s_hi = 0.f, q_hi = 0.f;
            #pragma unroll
            for (int nt = 0; nt < 8; nt++) {
                s_lo += acc[nt][0] + acc[nt][1];
                q_lo += acc[nt][0]*acc[nt][0] + acc[nt][1]*acc[nt][1];
                s_hi += acc[nt][2] + acc[nt][3];
                q_hi += acc[nt][2]*acc[nt][2] + acc[nt][3]*acc[nt][3];
            }
            #pragma unroll
            for (int o = 1; o <= 2; o <<= 1) {
                s_lo += __shfl_xor_sync(0xffffffffu, s_lo, o);
                q_lo += __shfl_xor_sync(0xffffffffu, q_lo, o);
                s_hi += __shfl_xor_sync(0xffffffffu, s_hi, o);
                q_hi += __shfl_xor_sync(0xffffffffu, q_hi, o);
            }
            float mu_lo = s_lo * (1.0f/64.0f);
            float mu_hi = s_hi * (1.0f/64.0f);
            float r_l   = rsqrtf(fmaxf(q_lo * (1.0f/64.0f) - mu_lo*mu_lo, 0.0f) + EPSF);
            float r_h   = rsqrtf(fmaxf(q_hi * (1.0f/64.0f) - mu_hi*mu_hi, 0.0f) + EPSF);

            #pragma unroll
            for (int nt = 0; nt < 8; nt++) {
                int c0 = nt * 8 + 2 * q;
                float2 g = *(float2*)(g3s + c0);
                float2 b = *(float2*)(b3s + c0);
                float h0 = (acc[nt][0] - mu_lo) * r_l * g.x + b.x;
                float h1 = (acc[nt][1] - mu_lo) * r_l * g.y + b.y;
                float h2 = (acc[nt][2] - mu_hi) * r_h * g.x + b.x;
                float h3 = (acc[nt][3] - mu_hi) * r_h * g.y + b.y;
                h0 = h0 > 0.f ? h0 : SLOPEF * h0;
                h1 = h1 > 0.f ? h1 : SLOPEF * h1;
                h2 = h2 > 0.f ? h2 : SLOPEF * h2;
                h3 = h3 > 0.f ? h3 : SLOPEF * h3;
                AB[rp * APS2 + 4 * nt + q] = make_uint2(hf2(h1, h0), hf2(h3, h2));
            }
        }
        __syncwarp();

        // ===== GEMM3 =====
        #pragma unroll
        for (int nt = 0; nt < 8; nt++)
            #pragma unroll
            for (int j = 0; j < 4; j++) acc[nt][j] = 0.0f;
        {
            const uint2* Ab = AB + rp * APS2;
            #pragma unroll
            for (int kt = 0; kt < 4; kt++) {
                uint4 av = *(const uint4*)(Ab + 8 * kt + 2 * q);
                const uint4* wrow = w3p4 + (kt * 4 + q) * WP4 + grp;
                #pragma unroll
                for (int p = 0; p < 4; p++) {
                    uint4 b4 = wrow[p * 8];
                    mma_f16(acc[2*p],   av.x, av.y, av.z, av.w, b4.x, b4.y);
                    mma_f16(acc[2*p+1], av.x, av.y, av.z, av.w, b4.z, b4.w);
                }
            }
        }
        __syncwarp();

        // ---- epilogue ----
        {
            unsigned* outu = (unsigned*)out;
            const int rs = wid * 16;
            const int t0 = tgs[rs];
            if (t0 >= 0 && tgs[rs + 15] == t0) {
                // fast path: all 16 rows same target; packed f16x2 max-reduce
                #pragma unroll
                for (int nt = 0; nt < 8; nt++) {
                    uint32_t va = hf2(acc[nt][1], acc[nt][0]);
                    uint32_t vb = hf2(acc[nt][3], acc[nt][2]);
                    __half2 m2 = __hmax2(*(__half2*)&va, *(__half2*)&vb);
                    #pragma unroll
                    for (int o = 4; o <= 16; o <<= 1) {
                        uint32_t mr = __shfl_xor_sync(0xffffffffu, *(uint32_t*)&m2, o);
                        m2 = __hmax2(m2, *(__half2*)&mr);
                    }
                    if (grp == 0) {
                        unsigned base = (unsigned)t0 * HID + nt * 8 + 2 * q;
                        atomicMax(outu + base,     fkey(__low2float(m2)));
                        atomicMax(outu + base + 1, fkey(__high2float(m2)));
                    }
                }
            } else {
                // slow path: f16x2 staging + run-aggregated hmax2 sweep
                #pragma unroll
                for (int nt = 0; nt < 8; nt++) {
                    int cp = 4 * nt + q;
                    MS16[r_lo * MS4 + cp] = hf2(acc[nt][1], acc[nt][0]);
                    MS16[r_hi * MS4 + cp] = hf2(acc[nt][3], acc[nt][2]);
                }
                __syncwarp();
                const int cp = lane;   // column pair -> cols 2cp, 2cp+1
                uint32_t mpk = H2_NEG_INF;
                __half2 mh = *(__half2*)&mpk;
                int cur = tgs[rs];
                #pragma unroll 4
                for (int r = rs; r < rs + 16; r++) {
                    int tg2 = tgs[r];
                    if (tg2 != cur) {
                        if (cur >= 0) {
                            unsigned base = (unsigned)cur * HID + 2 * cp;
                            atomicMax(outu + base,     fkey(__low2float(mh)));
                            atomicMax(outu + base + 1, fkey(__high2float(mh)));
                        }
                        cur = tg2;
                        mh = *(__half2*)&mpk;
                    }
                    uint32_t v = MS16[r * MS4 + cp];
                    mh = __hmax2(mh, *(__half2*)&v);
                }
                if (cur >= 0) {
                    unsigned base = (unsigned)cur * HID + 2 * cp;
                    atomicMax(outu + base,     fkey(__low2float(mh)));
                    atomicMax(outu + base + 1, fkey(__high2float(mh)));
                }
            }
        }
    }
    #undef LOAD_META
}

extern "C" void kernel_launch(void* const* d_in, const int* in_sizes, int n_in,
                              void* d_out, int out_size) {
    const float* x  = (const float*)d_in[0];
    const float* ew = (const float*)d_in[1];
    const int*   ei = (const int*)d_in[2];
    const float* w1 = (const float*)d_in[3];
    const float* w2 = (const float*)d_in[4];
    const float* w3 = (const float*)d_in[5];
    const float* g1 = (const float*)d_in[6];
    const float* b1 = (const float*)d_in[7];
    const float* g2 = (const float*)d_in[8];
    const float* b2 = (const float*)d_in[9];
    const float* g3 = (const float*)d_in[10];
    const float* b3 = (const float*)d_in[11];
    float* out = (float*)d_out;

    const int E  = in_sizes[1];
    const int NH = out_size;
    const int N  = NH / HID;
    const int n  = N + 1;
    const int nchunk = (n + SCAN_CHUNK - 1) / SCAN_CHUNK;
    const int ntiles = (E + TILE - 1) / TILE;
    const int nxh2 = N * (HID / 2);   // half2 count

    int nsm = 148;
    cudaDeviceGetAttribute(&nsm, cudaDevAttrMultiProcessorCount, 0);
    int nblocks = 2 * nsm;
    if (nblocks > ntiles) nblocks = ntiles;
    int ssblocks = 4 * nsm;

    cudaFuncSetAttribute(edge_kernel, cudaFuncAttributeMaxDynamicSharedMemorySize, SMEM_BYTES);

    int zi_n = n;
    if (NH / 4 > zi_n) zi_n = NH / 4;
    if (nxh2 > zi_n) zi_n = nxh2;
    zero_init_kernel<<<(zi_n + 255) / 256, 256>>>(n, (uint4*)out, NH / 4,
                                                  (const float2*)x, nxh2);       // #1
    hist_kernel<<<(E + 255) / 256, 256>>>(ei, E);                                 // #2
    scan_scatter_kernel<<<ssblocks, 256>>>(ei, E, n, nchunk);                     // #3
    edge_kernel<<<nblocks, NTHR, SMEM_BYTES>>>(                                   // #4 (profiled)
        x, ew, ei, w1, w2, w3, g1, b1, g2, b2, g3, b3, out, E, ntiles);
    finalize_kernel<<<(NH + 255) / 256, 256>>>(x, out, NH);                       // #5
}